// round 8
// baseline (speedup 1.0000x reference)
#include <cuda_runtime.h>
#include <stdint.h>

// x [n,c,h,w] fp32; per (n,c) row of hw=4096 keep top-k by |x|.
// out = x (kept) or x*(1-tau) (dropped).
// One CTA (512 thr) handles TWO rows under a single shared barrier schedule:
// radix pass0+pass1 (8b each) on key = bits<<1, gather <=128 candidates of
// the crossing 16-bit class per row, warps 0/1 ballot-binary-search the low
// 16 bits of row A/B in parallel. Radix passes 2-3 as rare fallback.

constexpr int HW      = 4096;
constexpr int THREADS = 512;
constexpr int EPT     = HW / THREADS;   // 8 per row
constexpr int NW      = THREADS / 32;   // 16 warps
constexpr int CAP     = 128;
constexpr unsigned FULL = 0xFFFFFFFFu;

__global__ __launch_bounds__(THREADS)
void topk_blend_kernel(const float* __restrict__ x,
                       const float* __restrict__ tau_p,
                       const int*   __restrict__ k_p,
                       float*       __restrict__ out)
{
    __shared__ uint32_t whist[2][NW][256];  // [row][warp-copy][bin]; bank=bin%32
    __shared__ uint32_t wsum[2][8];
    __shared__ uint32_t wtie[2][NW];
    __shared__ uint32_t list[2][CAP];
    __shared__ uint32_t s_T[2], s_krem[2], s_nlist[2], s_mode[2], s_fb[2];

    const int tid  = threadIdx.x;
    const int wid  = tid >> 5;
    const int lane = tid & 31;
    const size_t baseA = (size_t)(2 * blockIdx.x)     * HW;
    const size_t baseB = (size_t)(2 * blockIdx.x + 1) * HW;

    // ---- issue ALL loads up front: 4 LDG.128 in flight (2 rows x 2) ----
    uint32_t bA[EPT], bB[EPT];
    {
        const uint4* __restrict__ xa = reinterpret_cast<const uint4*>(x + baseA);
        const uint4* __restrict__ xb = reinterpret_cast<const uint4*>(x + baseB);
        uint4 a0 = xa[tid*2+0], a1 = xa[tid*2+1];
        uint4 b0 = xb[tid*2+0], b1 = xb[tid*2+1];
        bA[0]=a0.x; bA[1]=a0.y; bA[2]=a0.z; bA[3]=a0.w;
        bA[4]=a1.x; bA[5]=a1.y; bA[6]=a1.z; bA[7]=a1.w;
        bB[0]=b0.x; bB[1]=b0.y; bB[2]=b0.z; bB[3]=b0.w;
        bB[4]=b1.x; bB[5]=b1.y; bB[6]=b1.z; bB[7]=b1.w;
    }

    const float tau = __ldg(tau_p);
    const int   K   = __ldg(k_p);

    // zero hists: 2*16*256 = 8192 words / 512 thr = 4 uint4 per thread
    {
        uint4* hz = reinterpret_cast<uint4*>(&whist[0][0][0]);
        #pragma unroll
        for (int i = 0; i < 4; i++) hz[tid + 512*i] = make_uint4(0,0,0,0);
    }
    __syncthreads();                                             // B1

    uint32_t T0 = 0, T1 = 0;
    int need0 = 0, need1 = 0, excl0 = 0, excl1 = 0;
    bool geq0 = false, geq1 = false;
    const bool sel = (K > 0 && K < HW);

    if (sel) {
        const int half = tid >> 8;          // scan half: 0 = row A, 1 = row B
        const int hwid = wid & 7;           // warp index within half

        // ================= PASS 0 (key bits 31..24) =================
        {
            uint32_t* hA = &whist[0][wid][0];
            uint32_t* hB = &whist[1][wid][0];
            #pragma unroll
            for (int j = 0; j < EPT; j++) {
                uint32_t dig = (bA[j] >> 23) & 0xFFu;
                unsigned m = __match_any_sync(FULL, dig);
                if (lane == (int)__ffs(m) - 1)
                    atomicAdd(&hA[dig], (uint32_t)__popc(m));
            }
            #pragma unroll
            for (int j = 0; j < EPT; j++) {
                uint32_t dig = (bB[j] >> 23) & 0xFFu;
                unsigned m = __match_any_sync(FULL, dig);
                if (lane == (int)__ffs(m) - 1)
                    atomicAdd(&hB[dig], (uint32_t)__popc(m));
            }
        }
        __syncthreads();                                         // B2

        // reduce copies + suffix scan; half r handles row r's 256 bins
        {
            const int bin = tid & 255;
            uint32_t c = 0;
            #pragma unroll
            for (int w = 0; w < NW; w++) { c += whist[half][w][bin]; whist[half][w][bin] = 0; }
            uint32_t s = c;
            #pragma unroll
            for (int off = 1; off < 32; off <<= 1) {
                uint32_t v = __shfl_down_sync(FULL, s, off);
                if (lane + off < 32) s += v;
            }
            if (lane == 0) wsum[half][hwid] = s;
            __syncthreads();                                     // B3
            uint32_t hi = 0;
            #pragma unroll
            for (int w = 0; w < 8; w++) if (w > hwid) hi += wsum[half][w];
            uint32_t incl = s + hi, above = incl - c;
            uint32_t kr = (uint32_t)K;
            if (above < kr && kr <= incl) {
                s_T[half]    = (uint32_t)bin << 24;
                s_krem[half] = kr - above;
            }
        }
        __syncthreads();                                         // B4
        const uint32_t pref0 = s_T[0], pref1 = s_T[1];

        // ================= PASS 1 (key bits 23..16) =================
        uint32_t actA = 0, actB = 0;
        {
            uint32_t* hA = &whist[0][wid][0];
            uint32_t* hB = &whist[1][wid][0];
            const uint32_t phiA = pref0 >> 24, phiB = pref1 >> 24;
            #pragma unroll
            for (int j = 0; j < EPT; j++) {
                uint32_t key = bA[j] << 1;
                if ((key >> 24) == phiA) { actA |= 1u << j; atomicAdd(&hA[(key >> 16) & 0xFFu], 1u); }
            }
            #pragma unroll
            for (int j = 0; j < EPT; j++) {
                uint32_t key = bB[j] << 1;
                if ((key >> 24) == phiB) { actB |= 1u << j; atomicAdd(&hB[(key >> 16) & 0xFFu], 1u); }
            }
        }
        if (tid < 2) s_nlist[tid] = 0;
        __syncthreads();                                         // B5

        {
            const int bin = tid & 255;
            uint32_t c = 0;
            #pragma unroll
            for (int w = 0; w < NW; w++) { c += whist[half][w][bin]; whist[half][w][bin] = 0; }
            uint32_t s = c;
            #pragma unroll
            for (int off = 1; off < 32; off <<= 1) {
                uint32_t v = __shfl_down_sync(FULL, s, off);
                if (lane + off < 32) s += v;
            }
            if (lane == 0) wsum[half][hwid] = s;
            __syncthreads();                                     // B6
            uint32_t hi = 0;
            #pragma unroll
            for (int w = 0; w < 8; w++) if (w > hwid) hi += wsum[half][w];
            uint32_t incl = s + hi, above = incl - c;
            uint32_t kr = s_krem[half];
            if (above < kr && kr <= incl) {
                s_T[half]    = (half ? pref1 : pref0) | ((uint32_t)bin << 16);
                s_krem[half] = kr - above;
            }
        }
        __syncthreads();                                         // B7
        const uint32_t p16A = s_T[0] >> 16, p16B = s_T[1] >> 16;

        // ================= GATHER candidates (both rows) =============
        {
            uint32_t m = actA;
            while (m) {
                int j = __ffs(m) - 1; m &= m - 1;
                uint32_t key = bA[j] << 1;
                if ((key >> 16) == p16A) {
                    uint32_t pos = atomicAdd(&s_nlist[0], 1u);
                    if (pos < CAP) list[0][pos] = key & 0xFFFFu;
                }
            }
            m = actB;
            while (m) {
                int j = __ffs(m) - 1; m &= m - 1;
                uint32_t key = bB[j] << 1;
                if ((key >> 16) == p16B) {
                    uint32_t pos = atomicAdd(&s_nlist[1], 1u);
                    if (pos < CAP) list[1][pos] = key & 0xFFFFu;
                }
            }
        }
        __syncthreads();                                         // B8

        // ============ SEARCH: warp 0 -> row A, warp 1 -> row B =======
        if (wid < 2) {
            const int r = wid;
            const uint32_t nl = s_nlist[r];
            if (nl <= CAP) {
                const uint32_t krem   = s_krem[r];
                const uint32_t prefix = s_T[r];
                uint32_t v = 0, n_gt, n_eq;
                if (nl <= 32) {
                    const bool val = (lane < (int)nl);
                    const uint32_t cand = val ? list[r][lane] : 0u;
                    #pragma unroll
                    for (int bit = 15; bit >= 0; bit--) {
                        uint32_t t = v | (1u << bit);
                        uint32_t c = (uint32_t)__popc(__ballot_sync(FULL, val && cand >= t));
                        if (c >= krem) v = t;
                    }
                    n_gt = (uint32_t)__popc(__ballot_sync(FULL, val && cand >= v + 1));
                    n_eq = (uint32_t)__popc(__ballot_sync(FULL, val && cand >= v)) - n_gt;
                } else {
                    uint32_t cand[4]; bool val[4];
                    #pragma unroll
                    for (int i = 0; i < 4; i++) {
                        int idx = lane + 32 * i;
                        val[i]  = idx < (int)nl;
                        cand[i] = val[i] ? list[r][idx] : 0u;
                    }
                    auto cnt_ge = [&](uint32_t t) -> uint32_t {
                        uint32_t n = 0;
                        #pragma unroll
                        for (int i = 0; i < 4; i++)
                            n += (uint32_t)__popc(__ballot_sync(FULL, val[i] && cand[i] >= t));
                        return n;
                    };
                    #pragma unroll
                    for (int bit = 15; bit >= 0; bit--) {
                        uint32_t t = v | (1u << bit);
                        if (cnt_ge(t) >= krem) v = t;
                    }
                    n_gt = cnt_ge(v + 1);
                    n_eq = cnt_ge(v) - n_gt;
                }
                uint32_t need = krem - n_gt;
                if (lane == 0) {
                    s_T[r]    = prefix | v;
                    s_krem[r] = need;
                    s_mode[r] = (need == n_eq) ? 1u : 0u;
                    s_fb[r]   = 0u;
                }
            } else if (lane == 0) {
                s_mode[r] = 0u;
                s_fb[r]   = 1u;
            }
        }
        __syncthreads();                                         // B9

        // ============ FALLBACK radix passes 2-3 (rare) ===============
        if (s_fb[0] | s_fb[1]) {
            const bool fbr = (s_fb[half] != 0);
            #pragma unroll
            for (int pass = 2; pass < 4; pass++) {
                const int shift = 24 - 8 * pass;
                if (s_fb[0]) {
                    uint32_t* hA = &whist[0][wid][0];
                    const uint32_t phi = s_T[0] >> (shift + 8);
                    uint32_t nm = 0, m = actA;
                    while (m) {
                        int j = __ffs(m) - 1; m &= m - 1;
                        uint32_t key = bA[j] << 1;
                        if ((key >> (shift + 8)) == phi) { nm |= 1u << j; atomicAdd(&hA[(key >> shift) & 0xFFu], 1u); }
                    }
                    actA = nm;
                }
                if (s_fb[1]) {
                    uint32_t* hB = &whist[1][wid][0];
                    const uint32_t phi = s_T[1] >> (shift + 8);
                    uint32_t nm = 0, m = actB;
                    while (m) {
                        int j = __ffs(m) - 1; m &= m - 1;
                        uint32_t key = bB[j] << 1;
                        if ((key >> (shift + 8)) == phi) { nm |= 1u << j; atomicAdd(&hB[(key >> shift) & 0xFFu], 1u); }
                    }
                    actB = nm;
                }
                __syncthreads();

                const int bin = tid & 255;
                uint32_t c = 0;
                #pragma unroll
                for (int w = 0; w < NW; w++) { c += whist[half][w][bin]; whist[half][w][bin] = 0; }
                uint32_t s = c;
                #pragma unroll
                for (int off = 1; off < 32; off <<= 1) {
                    uint32_t v = __shfl_down_sync(FULL, s, off);
                    if (lane + off < 32) s += v;
                }
                if (lane == 0) wsum[half][hwid] = s;
                __syncthreads();
                if (fbr) {
                    uint32_t hi = 0;
                    #pragma unroll
                    for (int w = 0; w < 8; w++) if (w > hwid) hi += wsum[half][w];
                    uint32_t incl = s + hi, above = incl - c;
                    uint32_t kr = s_krem[half];
                    if (above < kr && kr <= incl) {
                        s_T[half]    = s_T[half] | ((uint32_t)bin << shift);
                        s_krem[half] = kr - above;
                    }
                }
                __syncthreads();
            }
        }

        T0 = s_T[0]; T1 = s_T[1];
        need0 = (int)s_krem[0]; need1 = (int)s_krem[1];
        geq0 = (s_mode[0] != 0); geq1 = (s_mode[1] != 0);

        // ============ TIE RANK (rare; uniform participation) =========
        if (!geq0 || !geq1) {
            int eqA = 0, eqB = 0;
            if (!geq0) {
                #pragma unroll
                for (int j = 0; j < EPT; j++) eqA += ((bA[j] << 1) == T0);
            }
            if (!geq1) {
                #pragma unroll
                for (int j = 0; j < EPT; j++) eqB += ((bB[j] << 1) == T1);
            }
            uint32_t ea = (uint32_t)eqA, eb = (uint32_t)eqB;
            #pragma unroll
            for (int off = 1; off < 32; off <<= 1) {
                uint32_t va = __shfl_up_sync(FULL, ea, off);
                uint32_t vb = __shfl_up_sync(FULL, eb, off);
                if (lane >= off) { ea += va; eb += vb; }
            }
            if (lane == 31) { wtie[0][wid] = ea; wtie[1][wid] = eb; }
            __syncthreads();
            uint32_t loA = 0, loB = 0;
            #pragma unroll
            for (int w = 0; w < NW; w++) if (w < wid) { loA += wtie[0][w]; loB += wtie[1][w]; }
            excl0 = (int)(ea - (uint32_t)eqA + loA);
            excl1 = (int)(eb - (uint32_t)eqB + loB);
        }
    }

    // ================ APPLY both rows ================
    const float omt = 1.0f - tau;
    const bool keepall = (K >= HW);
    {
        const float Tf = __uint_as_float(T0 >> 1);
        float4* __restrict__ y = reinterpret_cast<float4*>(out + baseA);
        int rank = excl0;
        #pragma unroll
        for (int i = 0; i < 2; i++) {
            float r[4];
            #pragma unroll
            for (int j = 0; j < 4; j++) {
                const int idx = i * 4 + j;
                float xv = __uint_as_float(bA[idx]);
                bool keep;
                if (!sel)       keep = keepall;
                else if (geq0)  keep = (fabsf(xv) >= Tf);
                else {
                    uint32_t key = bA[idx] << 1;
                    keep = (key > T0) | ((key == T0) & (rank < need0));
                    rank += (key == T0);
                }
                r[j] = keep ? xv : xv * omt;
            }
            y[tid*2+i] = make_float4(r[0], r[1], r[2], r[3]);
        }
    }
    {
        const float Tf = __uint_as_float(T1 >> 1);
        float4* __restrict__ y = reinterpret_cast<float4*>(out + baseB);
        int rank = excl1;
        #pragma unroll
        for (int i = 0; i < 2; i++) {
            float r[4];
            #pragma unroll
            for (int j = 0; j < 4; j++) {
                const int idx = i * 4 + j;
                float xv = __uint_as_float(bB[idx]);
                bool keep;
                if (!sel)       keep = keepall;
                else if (geq1)  keep = (fabsf(xv) >= Tf);
                else {
                    uint32_t key = bB[idx] << 1;
                    keep = (key > T1) | ((key == T1) & (rank < need1));
                    rank += (key == T1);
                }
                r[j] = keep ? xv : xv * omt;
            }
            y[tid*2+i] = make_float4(r[0], r[1], r[2], r[3]);
        }
    }
}

extern "C" void kernel_launch(void* const* d_in, const int* in_sizes, int n_in,
                              void* d_out, int out_size)
{
    const float* x   = (const float*)d_in[0];
    const float* tau = (const float*)d_in[1];
    const int*   k   = (const int*)d_in[2];
    float*       out = (float*)d_out;
    const int    rows = in_sizes[0] / HW;   // n*c = 8192 (even)

    topk_blend_kernel<<<rows / 2, THREADS>>>(x, tau, k, out);
}

// round 9
// speedup vs baseline: 1.5647x; 1.5647x over previous
#include <cuda_runtime.h>
#include <stdint.h>

// x [n,c,h,w] fp32; per (n,c) row of hw=4096 keep top-k by |x|.
// out = x (kept) or x*(1-tau) (dropped).
// One CTA (256 thr) per row, data register-resident (key = bits<<1).
// Select: 11-bit histogram (2048 bins) -> gather crossing class (<=256) ->
// 8-bit histogram over the list -> gather subclass (<=64) -> 13-bit
// single-warp ballot search. Exact cold fallback: counting binary search.

constexpr int HW      = 4096;
constexpr int THREADS = 256;
constexpr int EPT     = HW / THREADS;    // 16
constexpr int NBIN    = 2048;
constexpr int BPT     = NBIN / THREADS;  // 8 bins per thread
constexpr int CAP1    = 256;
constexpr int CAP2    = 64;
constexpr unsigned FULL = 0xFFFFFFFFu;

__global__ __launch_bounds__(THREADS)
void topk_blend_kernel(const float* __restrict__ x,
                       const float* __restrict__ tau_p,
                       const int*   __restrict__ k_p,
                       float*       __restrict__ out)
{
    __shared__ uint32_t hist[NBIN];
    __shared__ uint32_t wtot[8];
    __shared__ uint32_t wtie[8];
    __shared__ uint32_t list1[CAP1];     // 21-bit remainders
    __shared__ uint32_t list2[CAP2];     // 13-bit remainders
    __shared__ uint32_t s_bin, s_krem, s_n1, s_n2, s_T, s_need, s_mode, s_cnt;

    const int tid  = threadIdx.x;
    const int wid  = tid >> 5;
    const int lane = tid & 31;
    const size_t base = (size_t)blockIdx.x * HW;

    // Blocked vectorized load: thread t owns elements [t*16, t*16+16)
    uint32_t b[EPT];
    const uint4* __restrict__ xin = reinterpret_cast<const uint4*>(x + base);
    #pragma unroll
    for (int i = 0; i < 4; i++) {
        uint4 v = xin[tid * 4 + i];
        b[i*4+0] = v.x; b[i*4+1] = v.y; b[i*4+2] = v.z; b[i*4+3] = v.w;
    }

    const float tau = __ldg(tau_p);
    const int   K   = __ldg(k_p);

    // zero hist: 2048 words / 256 thr = 2 x uint4 per thread
    reinterpret_cast<uint4*>(hist)[tid*2+0] = make_uint4(0,0,0,0);
    reinterpret_cast<uint4*>(hist)[tid*2+1] = make_uint4(0,0,0,0);
    __syncthreads();                                            // B1

    uint32_t T = 0, need = 0;
    int  t_excl = 0;
    bool geq = false;
    const bool sel = (K > 0 && K < HW);

    if (sel) {
        // ========== 11-bit histogram (key bits 31..21) ==========
        #pragma unroll
        for (int j = 0; j < EPT; j++)
            atomicAdd(&hist[(b[j] >> 20) & 0x7FFu], 1u);
        __syncthreads();                                        // B2

        // ========== scan over 2048 bins ==========
        {
            const int b0 = tid * BPT;
            uint4 h0 = reinterpret_cast<uint4*>(hist)[tid*2+0];
            uint4 h1 = reinterpret_cast<uint4*>(hist)[tid*2+1];
            reinterpret_cast<uint4*>(hist)[tid*2+0] = make_uint4(0,0,0,0);
            reinterpret_cast<uint4*>(hist)[tid*2+1] = make_uint4(0,0,0,0);
            uint32_t c[8] = {h0.x,h0.y,h0.z,h0.w,h1.x,h1.y,h1.z,h1.w};
            uint32_t suf[8];
            suf[7] = c[7];
            #pragma unroll
            for (int i = 6; i >= 0; i--) suf[i] = c[i] + suf[i+1];
            const uint32_t tot = suf[0];

            uint32_t s = tot;                      // inclusive suffix over lanes
            #pragma unroll
            for (int off = 1; off < 32; off <<= 1) {
                uint32_t v = __shfl_down_sync(FULL, s, off);
                if (lane + off < 32) s += v;
            }
            const uint32_t lane_hi = s - tot;      // lanes > lane
            if (lane == 0) wtot[wid] = s;          // warp total
            __syncthreads();                                    // B3

            uint32_t warp_hi = 0;
            #pragma unroll
            for (int w = 0; w < 8; w++) if (w > wid) warp_hi += wtot[w];
            const uint32_t off = lane_hi + warp_hi;
            const uint32_t Ku = (uint32_t)K;
            #pragma unroll
            for (int i = 0; i < 8; i++) {
                uint32_t incl  = suf[i] + off;     // count of keys with bin >= b0+i
                uint32_t above = incl - c[i];
                if (above < Ku && Ku <= incl) {    // exactly one (thread,i)
                    s_bin  = (uint32_t)(b0 + i);
                    s_krem = Ku - above;
                }
            }
            if (tid == 0) s_n1 = 0;
        }
        __syncthreads();                                        // B4

        const uint32_t binsel = s_bin;
        const uint32_t krem1  = s_krem;

        // ========== gather crossing-class candidates ==========
        #pragma unroll
        for (int j = 0; j < EPT; j++) {
            uint32_t key = b[j] << 1;
            if ((key >> 21) == binsel) {
                uint32_t pos = atomicAdd(&s_n1, 1u);
                if (pos < CAP1) list1[pos] = key & 0x1FFFFFu;
            }
        }
        __syncthreads();                                        // B5
        const uint32_t n1 = s_n1;

        if (n1 <= CAP1) {
            // ===== 8-bit histogram over the list (bits 20..13) =====
            for (uint32_t i = tid; i < n1; i += THREADS)
                atomicAdd(&hist[(list1[i] >> 13) & 0xFFu], 1u);
            __syncthreads();                                    // B6

            // ===== scan 256 bins (one per thread) =====
            {
                uint32_t c2 = hist[tid];
                hist[tid] = 0;
                uint32_t s2 = c2;
                #pragma unroll
                for (int off = 1; off < 32; off <<= 1) {
                    uint32_t v = __shfl_down_sync(FULL, s2, off);
                    if (lane + off < 32) s2 += v;
                }
                if (lane == 0) wtot[wid] = s2;
                __syncthreads();                                // B7
                uint32_t hi2 = 0;
                #pragma unroll
                for (int w = 0; w < 8; w++) if (w > wid) hi2 += wtot[w];
                uint32_t incl2  = s2 + hi2;
                uint32_t above2 = incl2 - c2;
                if (above2 < krem1 && krem1 <= incl2) {
                    s_bin  = (uint32_t)tid;
                    s_krem = krem1 - above2;
                }
                if (tid == 0) s_n2 = 0;
            }
            __syncthreads();                                    // B8

            const uint32_t bin2  = s_bin;
            const uint32_t krem2 = s_krem;

            // ===== gather subclass =====
            for (uint32_t i = tid; i < n1; i += THREADS) {
                uint32_t v = list1[i];
                if (((v >> 13) & 0xFFu) == bin2) {
                    uint32_t pos = atomicAdd(&s_n2, 1u);
                    if (pos < CAP2) list2[pos] = v & 0x1FFFu;
                }
            }
            __syncthreads();                                    // B9
            const uint32_t n2 = s_n2;

            if (n2 <= CAP2) {
                // ===== single-warp 13-bit ballot search =====
                if (wid == 0) {
                    uint32_t cand[2]; bool val[2];
                    #pragma unroll
                    for (int i = 0; i < 2; i++) {
                        int idx = lane + 32 * i;
                        val[i]  = idx < (int)n2;
                        cand[i] = val[i] ? list2[idx] : 0u;
                    }
                    auto cnt_ge = [&](uint32_t t) -> uint32_t {
                        uint32_t n = 0;
                        #pragma unroll
                        for (int i = 0; i < 2; i++)
                            n += (uint32_t)__popc(__ballot_sync(FULL, val[i] && cand[i] >= t));
                        return n;
                    };
                    uint32_t v = 0;
                    #pragma unroll
                    for (int bit = 12; bit >= 0; bit--) {
                        uint32_t t = v | (1u << bit);
                        if (cnt_ge(t) >= krem2) v = t;
                    }
                    uint32_t n_gt = cnt_ge(v + 1);
                    uint32_t n_eq = cnt_ge(v) - n_gt;
                    uint32_t nd   = krem2 - n_gt;           // >= 1
                    if (lane == 0) {
                        s_T    = (binsel << 21) | (bin2 << 13) | v;
                        s_need = nd;
                        s_mode = (nd == n_eq) ? 1u : 0u;
                    }
                }
            } else {
                if (tid == 0) s_mode = 2u;                   // fallback
            }
            __syncthreads();                                // B10
        } else {
            if (tid == 0) s_mode = 2u;
            __syncthreads();                                // B10'
        }

        const uint32_t mode = s_mode;
        if (mode != 2u) {
            T    = s_T;
            need = s_need;
            geq  = (mode == 1u);
        } else {
            // ===== exact cold fallback: counting binary search on full key =====
            uint32_t Tf = 0;
            const uint32_t Ku = (uint32_t)K;
            for (int bit = 30; bit >= 0; bit--) {
                if (tid == 0) s_cnt = 0;
                __syncthreads();
                uint32_t trial = Tf | (1u << bit);
                uint32_t cnt = 0;
                #pragma unroll
                for (int j = 0; j < EPT; j++) cnt += ((b[j] << 1) >= trial);
                #pragma unroll
                for (int off = 16; off >= 1; off >>= 1)
                    cnt += __shfl_down_sync(FULL, cnt, off);
                if (lane == 0) atomicAdd(&s_cnt, cnt);
                __syncthreads();
                if (s_cnt >= Ku) Tf = trial;
                __syncthreads();
            }
            // tie counts
            uint32_t n_ge = 0, n_gt = 0;
            {
                if (tid == 0) s_cnt = 0;
                __syncthreads();
                uint32_t cnt = 0;
                #pragma unroll
                for (int j = 0; j < EPT; j++) cnt += ((b[j] << 1) >= Tf);
                #pragma unroll
                for (int off = 16; off >= 1; off >>= 1)
                    cnt += __shfl_down_sync(FULL, cnt, off);
                if (lane == 0) atomicAdd(&s_cnt, cnt);
                __syncthreads();
                n_ge = s_cnt;
                __syncthreads();
                if (tid == 0) s_cnt = 0;
                __syncthreads();
                cnt = 0;
                #pragma unroll
                for (int j = 0; j < EPT; j++) cnt += ((b[j] << 1) > Tf);
                #pragma unroll
                for (int off = 16; off >= 1; off >>= 1)
                    cnt += __shfl_down_sync(FULL, cnt, off);
                if (lane == 0) atomicAdd(&s_cnt, cnt);
                __syncthreads();
                n_gt = s_cnt;
            }
            T    = Tf;
            need = Ku - n_gt;
            geq  = (need == (n_ge - n_gt));
        }

        // ===== stable tie rank (only when threshold value duplicated) =====
        if (!geq) {
            int myeq = 0;
            #pragma unroll
            for (int j = 0; j < EPT; j++) myeq += ((b[j] << 1) == T);
            uint32_t e = (uint32_t)myeq;
            #pragma unroll
            for (int off = 1; off < 32; off <<= 1) {
                uint32_t v = __shfl_up_sync(FULL, e, off);
                if (lane >= off) e += v;
            }
            if (lane == 31) wtie[wid] = e;
            __syncthreads();
            uint32_t lo = 0;
            #pragma unroll
            for (int w = 0; w < 8; w++) if (w < wid) lo += wtie[w];
            t_excl = (int)(e - (uint32_t)myeq + lo);
        }
    }

    // ========== apply: out = kept ? x : x*(1-tau) ==========
    const float omt = 1.0f - tau;
    float4* __restrict__ yout = reinterpret_cast<float4*>(out + base);
    int rank = t_excl;
    const int needi = (int)need;
    #pragma unroll
    for (int i = 0; i < 4; i++) {
        float r[4];
        #pragma unroll
        for (int j = 0; j < 4; j++) {
            const int idx = i * 4 + j;
            uint32_t key = b[idx] << 1;
            bool keep;
            if (!sel)     keep = (K >= HW);
            else if (geq) keep = (key >= T);
            else {
                keep = (key > T) | ((key == T) & (rank < needi));
                rank += (key == T);
            }
            float xv = __uint_as_float(b[idx]);
            r[j] = keep ? xv : xv * omt;
        }
        yout[tid * 4 + i] = make_float4(r[0], r[1], r[2], r[3]);
    }
}

extern "C" void kernel_launch(void* const* d_in, const int* in_sizes, int n_in,
                              void* d_out, int out_size)
{
    const float* x   = (const float*)d_in[0];
    const float* tau = (const float*)d_in[1];
    const int*   k   = (const int*)d_in[2];
    float*       out = (float*)d_out;
    const int    rows = in_sizes[0] / HW;   // n*c = 8192

    topk_blend_kernel<<<rows, THREADS>>>(x, tau, k, out);
}